// round 15
// baseline (speedup 1.0000x reference)
#include <cuda_runtime.h>
#include <cuda_bf16.h>
#include <math.h>
#include <stdint.h>

// Problem dims
#define BATCH 256
#define TSTEPS 250
#define IDIM 700
#define HDIM 128
#define ODIM 20

// xin buffer: [B][T][H] fp32 = 32.77 MB
__device__ float g_xin[BATCH * TSTEPS * HDIM];

// Correctly-rounded float exp via double (matches glibc expf). Init-path only.
__device__ __forceinline__ float expd(float x)
{
    return (float)exp((double)x);
}

#define BARSYNC(id, cnt) asm volatile("bar.sync %0, %1;" :: "r"(id), "r"(cnt) : "memory")

// ---------------------------------------------------------------------------
// Kernel 1 (exact R9 version, 302us known-good): xin[m][h] =
// (sum_k x[m][k]*w[k][h]) + b[h], single fp32 acc, ascending k, bias last.
// Double-buffered smem pipeline. BM=64, BK=16, 256 threads.
// ---------------------------------------------------------------------------
#define BM 64
#define BK 16

__global__ __launch_bounds__(256) void gemm_xin_kernel(
    const float* __restrict__ X, const float* __restrict__ W,
    const float* __restrict__ bias)
{
    __shared__ float Xs[2][BK][BM];
    __shared__ float Ws[2][BK][HDIM];

    const int tid = threadIdx.x;
    const int m0 = blockIdx.x * BM;

    const int ty = tid >> 5;        // 0..7
    const int tx = tid & 31;        // 0..31
    const int mBase = ty * 8;       // 8 rows per thread
    const int nBase = tx * 4;       // 4 cols per thread

    float acc[8][4];
#pragma unroll
    for (int i = 0; i < 8; i++)
#pragma unroll
        for (int j = 0; j < 4; j++) acc[i][j] = 0.f;

    const int lr = tid >> 2;          // 0..63 (X tile row)
    const int lc = (tid & 3) * 4;     // X tile k chunk
    const int wr = tid >> 5;          // 0..7 (W tile row)
    const int wc = (tid & 31) * 4;    // W tile col chunk

    const int NT = (IDIM + BK - 1) / BK;   // 44

#pragma unroll
    for (int i = 0; i < 4; i++) {
        int k = lc + i;
        Xs[0][lc + i][lr] = (k < IDIM) ? X[(size_t)(m0 + lr) * IDIM + k] : 0.f;
    }
#pragma unroll
    for (int rr = 0; rr < 2; rr++) {
        int k = wr + rr * 8;
        float4 v = make_float4(0.f, 0.f, 0.f, 0.f);
        if (k < IDIM) v = *(const float4*)&W[(size_t)k * HDIM + wc];
        *(float4*)&Ws[0][wr + rr * 8][wc] = v;
    }
    __syncthreads();

    int buf = 0;
    for (int kt = 0; kt < NT; kt++) {
        const bool has_next = (kt + 1) < NT;
        const int k0n = (kt + 1) * BK;

        float xr[4];
        float4 wv[2];
        if (has_next) {
#pragma unroll
            for (int i = 0; i < 4; i++) {
                int k = k0n + lc + i;
                xr[i] = (k < IDIM) ? X[(size_t)(m0 + lr) * IDIM + k] : 0.f;
            }
#pragma unroll
            for (int rr = 0; rr < 2; rr++) {
                int k = k0n + wr + rr * 8;
                wv[rr] = make_float4(0.f, 0.f, 0.f, 0.f);
                if (k < IDIM) wv[rr] = *(const float4*)&W[(size_t)k * HDIM + wc];
            }
        }

#pragma unroll
        for (int k = 0; k < BK; k++) {   // strictly ascending k
            float4 x0 = *(float4*)&Xs[buf][k][mBase];
            float4 x1 = *(float4*)&Xs[buf][k][mBase + 4];
            float4 w4 = *(float4*)&Ws[buf][k][nBase];
            float xv[8] = {x0.x, x0.y, x0.z, x0.w, x1.x, x1.y, x1.z, x1.w};
            float wvv[4] = {w4.x, w4.y, w4.z, w4.w};
#pragma unroll
            for (int i = 0; i < 8; i++)
#pragma unroll
                for (int j = 0; j < 4; j++)
                    acc[i][j] = fmaf(xv[i], wvv[j], acc[i][j]);
        }

        if (has_next) {
            int nb = buf ^ 1;
#pragma unroll
            for (int i = 0; i < 4; i++) Xs[nb][lc + i][lr] = xr[i];
#pragma unroll
            for (int rr = 0; rr < 2; rr++)
                *(float4*)&Ws[nb][wr + rr * 8][wc] = wv[rr];
            __syncthreads();
            buf = nb;
        }
    }

    float4 bb = *(const float4*)&bias[nBase];
#pragma unroll
    for (int i = 0; i < 8; i++) {
        float4 r;
        r.x = __fadd_rn(acc[i][0], bb.x);
        r.y = __fadd_rn(acc[i][1], bb.y);
        r.z = __fadd_rn(acc[i][2], bb.z);
        r.w = __fadd_rn(acc[i][3], bb.w);
        *(float4*)&g_xin[(size_t)(m0 + mBase + i) * HDIM + nBase] = r;
    }
}

// ---------------------------------------------------------------------------
// Kernel 2: A_norm
// ---------------------------------------------------------------------------
__global__ void anorm_kernel(const float* __restrict__ w11,
                             const float* __restrict__ w22,
                             const float* __restrict__ mask,
                             float* __restrict__ out)
{
    __shared__ float redA[256];
    __shared__ float redB[256];
    int tid = threadIdx.x;
    float sa = 0.f, sb = 0.f;
    for (int i = tid; i < HDIM * HDIM; i += 256) {
        sa += fabsf(__fmul_rn(w11[i], mask[i]));
        sb += fabsf(__fmul_rn(w22[i], mask[HDIM * HDIM + i]));
    }
    redA[tid] = sa;
    redB[tid] = sb;
    __syncthreads();
    for (int o = 128; o > 0; o >>= 1) {
        if (tid < o) { redA[tid] += redA[tid + o]; redB[tid] += redB[tid + o]; }
        __syncthreads();
    }
    if (tid == 0)
        out[BATCH * ODIM + 2 * BATCH * HDIM] = __fadd_rn(redA[0], redB[0]);
}

// ---------------------------------------------------------------------------
// Kernel 3: persistent scan. grid = 128 blocks x 320 threads.
// ROW-SPLIT warp specialization: warps 0-3 compute batch row r0 (thread=h),
// warps 4-7 compute row r1, warps 8-9 pipelined readout (one per row,
// one step behind on the double-buffered s2 arrays).
// 2 compute warps per SMSP -> mutual LDS-latency hiding.
// Numerics: per-(row,h) single fp32 accumulator, ascending j -> bit-exact.
// ---------------------------------------------------------------------------
__device__ __forceinline__ void dot_single(const float* __restrict__ W,
                                           const float* __restrict__ s,
                                           int h, float& a0)
{
#pragma unroll 8
    for (int j = 0; j < HDIM; j += 4) {
        float4 va = *(const float4*)(s + j);
        float w0 = W[(j + 0) * HDIM + h];
        float w1 = W[(j + 1) * HDIM + h];
        float w2 = W[(j + 2) * HDIM + h];
        float w3 = W[(j + 3) * HDIM + h];
        a0 = fmaf(va.x, w0, a0);
        a0 = fmaf(va.y, w1, a0);
        a0 = fmaf(va.z, w2, a0);
        a0 = fmaf(va.w, w3, a0);
    }
}

#define SM_W11 0
#define SM_W12 (HDIM * HDIM)
#define SM_W22 (2 * HDIM * HDIM)
#define SM_W2O (3 * HDIM * HDIM)
#define SM_S1  (3 * HDIM * HDIM + HDIM * ODIM)   // [2 phase][2 row][128]
#define SM_S2  (SM_S1 + 4 * HDIM)
#define SMEM_FLOATS (SM_S2 + 4 * HDIM)

#define NTHREADS_SCAN 320
#define NCOMPUTE 256

__global__ __launch_bounds__(NTHREADS_SCAN) void scan_kernel(
    const float* __restrict__ mask,
    const float* __restrict__ w_h1h1, const float* __restrict__ b_h1h1,
    const float* __restrict__ w_h1h2, const float* __restrict__ b_h1h2,
    const float* __restrict__ w_h2h2, const float* __restrict__ b_h2h2,
    const float* __restrict__ w_h2o,  const float* __restrict__ b_h2o,
    const float* __restrict__ tau_adp_h1, const float* __restrict__ tau_adp_h2,
    const float* __restrict__ tau_m_h1,   const float* __restrict__ tau_m_h2,
    const float* __restrict__ tau_m_o,
    const float* __restrict__ hid1_mem0, const float* __restrict__ hid2_mem0,
    const float* __restrict__ out_mem0,
    float* __restrict__ out)
{
    extern __shared__ float sm[];
    float* w11 = sm + SM_W11;
    float* w12 = sm + SM_W12;
    float* w22 = sm + SM_W22;
    float* w2o = sm + SM_W2O;
    float* s1b = sm + SM_S1;   // [phase][row][128]
    float* s2b = sm + SM_S2;

    const int tid = threadIdx.x;
    const int r0 = blockIdx.x * 2;

    for (int idx = tid; idx < HDIM * HDIM; idx += NTHREADS_SCAN) {
        w11[idx] = __fmul_rn(w_h1h1[idx], mask[idx]);
        w12[idx] = w_h1h2[idx];
        w22[idx] = __fmul_rn(w_h2h2[idx], mask[HDIM * HDIM + idx]);
    }
    for (int idx = tid; idx < HDIM * ODIM; idx += NTHREADS_SCAN)
        w2o[idx] = w_h2o[idx];

    if (tid < NCOMPUTE) {
        // ============ compute warps: 0-3 -> row 0, 4-7 -> row 1 ============
        const int row = tid >> 7;        // 0 or 1
        const int h = tid & 127;
        const int r = r0 + row;
        const int rowoff = row * HDIM;

        const float a1  = expd(__fdiv_rn(-1.0f, tau_m_h1[h]));
        const float r1d = expd(__fdiv_rn(-1.0f, tau_adp_h1[h]));
        const float a2  = expd(__fdiv_rn(-1.0f, tau_m_h2[h]));
        const float r2d = expd(__fdiv_rn(-1.0f, tau_adp_h2[h]));
        const float om_a1  = __fsub_rn(1.0f, a1);
        const float om_r1d = __fsub_rn(1.0f, r1d);
        const float om_a2  = __fsub_rn(1.0f, a2);
        const float om_r2d = __fsub_rn(1.0f, r2d);
        const float bh11 = b_h1h1[h];
        const float b12  = b_h1h2[h];
        const float b22c = b_h2h2[h];

        float h1m = hid1_mem0[r * HDIM + h];
        float h2m = hid2_mem0[r * HDIM + h];
        float b1 = 0.01f, b2 = 0.01f;
        float s1reg = 0.f, s2reg = 0.f;
        float s1c = 0.f, s2c = 0.f;

        // zero phase-0 spike buffers (this thread's slot)
        s1b[rowoff + h] = 0.f;
        s2b[rowoff + h] = 0.f;

        __syncthreads();

        float xt = g_xin[((size_t)r * TSTEPS + 0) * HDIM + h];

        for (int t = 0; t < TSTEPS; t++) {
            const int rd = (t & 1) * 2 * HDIM;
            const int wr = ((t & 1) ^ 1) * 2 * HDIM;

            // ---- layer 1 ----
            float d11 = 0.f;
            dot_single(w11, s1b + rd + rowoff, h, d11);
            float i1 = __fadd_rn(__fadd_rn(xt, d11), bh11);
            if (t < TSTEPS - 1)
                xt = g_xin[((size_t)r * TSTEPS + t + 1) * HDIM + h];

            b1 = __fadd_rn(__fmul_rn(r1d, b1), __fmul_rn(om_r1d, s1reg));
            float B1 = __fadd_rn(0.01f, __fmul_rn(1.8f, b1));
            h1m = __fsub_rn(__fadd_rn(__fmul_rn(h1m, a1), __fmul_rn(om_a1, i1)),
                            __fmul_rn(B1, s1reg));
            float ns = __fsub_rn(h1m, B1) > 0.f ? 1.f : 0.f;
            s1c += ns;

            s1b[wr + rowoff + h] = ns;
            s1reg = ns;
            BARSYNC(1, NCOMPUTE);                // new s1 visible (compute only)

            // ---- layer 2 ----
            float d12 = 0.f;
            dot_single(w12, s1b + wr + rowoff, h, d12);
            float d22 = 0.f;
            dot_single(w22, s2b + rd + rowoff, h, d22);
            float i2 = __fadd_rn(__fadd_rn(__fadd_rn(d12, b12), d22), b22c);

            b2 = __fadd_rn(__fmul_rn(r2d, b2), __fmul_rn(om_r2d, s2reg));
            float B2 = __fadd_rn(0.01f, __fmul_rn(1.8f, b2));
            h2m = __fsub_rn(__fadd_rn(__fmul_rn(h2m, a2), __fmul_rn(om_a2, i2)),
                            __fmul_rn(B2, s2reg));
            float ms = __fsub_rn(h2m, B2) > 0.f ? 1.f : 0.f;
            s2c += ms;

            s2b[wr + rowoff + h] = ms;
            s2reg = ms;
            BARSYNC(2, NTHREADS_SCAN);           // step end: hand s2 to readout
        }

        out[BATCH * ODIM + r * HDIM + h] = __fdiv_rn(s1c, (float)TSTEPS);
        out[BATCH * ODIM + BATCH * HDIM + r * HDIM + h] = __fdiv_rn(s2c, (float)TSTEPS);
    } else {
        // ============ readout warps (8-9), one per row ============
        const int lane = tid & 31;
        const int row  = (tid >> 5) - 8;         // 0 or 1

        float om = 0.f, accv = 0.f, ao = 0.f, om_ao = 0.f, b2o = 0.f;
        if (lane < ODIM) {
            om    = out_mem0[(r0 + row) * ODIM + lane];
            ao    = expd(__fdiv_rn(-1.0f, tau_m_o[lane]));
            om_ao = __fsub_rn(1.0f, ao);
            b2o   = b_h2o[lane];
        }
        __syncthreads();

        for (int t = 0; t < TSTEPS; t++) {
            BARSYNC(2, NTHREADS_SCAN);           // s2 of step t is ready
            const int wr = ((t & 1) ^ 1) * 2 * HDIM;
            const float* ss = s2b + wr + row * HDIM;

            if (lane < ODIM) {
                float dio = 0.f;                 // ascending j, single acc
#pragma unroll 4
                for (int j = 0; j < HDIM; j++)
                    dio = fmaf(ss[j], w2o[j * ODIM + lane], dio);
                float io = __fadd_rn(dio, b2o);
                om = __fadd_rn(__fmul_rn(om, ao), __fmul_rn(om_ao, io));
            }
            // softmax over 20 logits: tree max (exact) + tree sum + expf
            // (feeds only output 0; ulp-level noise, no trajectory feedback)
            float v = (lane < ODIM) ? om : -3.4e38f;
#pragma unroll
            for (int off = 16; off > 0; off >>= 1)
                v = fmaxf(v, __shfl_xor_sync(0xffffffffu, v, off));
            float p = (lane < ODIM) ? expf(__fsub_rn(om, v)) : 0.f;
            float ssum = p;
#pragma unroll
            for (int off = 16; off > 0; off >>= 1)
                ssum = __fadd_rn(ssum, __shfl_xor_sync(0xffffffffu, ssum, off));
            if (lane < ODIM && t > 10)
                accv = __fadd_rn(accv, __fdiv_rn(p, ssum));
        }

        if (lane < ODIM)
            out[(r0 + row) * ODIM + lane] = accv;
    }
}

// ---------------------------------------------------------------------------
extern "C" void kernel_launch(void* const* d_in, const int* in_sizes, int n_in,
                              void* d_out, int out_size)
{
    const float* x         = (const float*)d_in[0];
    const float* mask      = (const float*)d_in[1];
    const float* w_ih1     = (const float*)d_in[2];
    const float* b_ih1     = (const float*)d_in[3];
    const float* w_h1h1    = (const float*)d_in[4];
    const float* b_h1h1    = (const float*)d_in[5];
    const float* w_h1h2    = (const float*)d_in[6];
    const float* b_h1h2    = (const float*)d_in[7];
    const float* w_h2h2    = (const float*)d_in[8];
    const float* b_h2h2    = (const float*)d_in[9];
    const float* w_h2o     = (const float*)d_in[10];
    const float* b_h2o     = (const float*)d_in[11];
    const float* tau_adp_h1= (const float*)d_in[12];
    const float* tau_adp_h2= (const float*)d_in[13];
    const float* tau_m_h1  = (const float*)d_in[14];
    const float* tau_m_h2  = (const float*)d_in[15];
    const float* tau_m_o   = (const float*)d_in[16];
    const float* hid1_mem0 = (const float*)d_in[17];
    const float* hid2_mem0 = (const float*)d_in[18];
    const float* out_mem0  = (const float*)d_in[19];
    float* out = (float*)d_out;

    gemm_xin_kernel<<<(BATCH * TSTEPS) / BM, 256>>>(x, w_ih1, b_ih1);

    anorm_kernel<<<1, 256>>>(w_h1h1, w_h2h2, mask, out);

    size_t smem = SMEM_FLOATS * sizeof(float);
    cudaFuncSetAttribute(scan_kernel,
                         cudaFuncAttributeMaxDynamicSharedMemorySize,
                         (int)smem);
    scan_kernel<<<BATCH / 2, NTHREADS_SCAN, smem>>>(
        mask, w_h1h1, b_h1h1, w_h1h2, b_h1h2, w_h2h2, b_h2h2,
        w_h2o, b_h2o, tau_adp_h1, tau_adp_h2, tau_m_h1, tau_m_h2,
        tau_m_o, hid1_mem0, hid2_mem0, out_mem0, out);
}